// round 10
// baseline (speedup 1.0000x reference)
#include <cuda_runtime.h>

// ---------------- problem constants ----------------
#define NZ     300
#define NX     400
#define NPML   32
#define NZP    (NZ + 2*NPML)            // 364
#define NXP    (NX + 2*NPML)            // 464
#define NXPP   480                      // global row pitch (floats)
#define NSTEPS 200
#define NSHOTS 2
#define DXC    0.01f
#define DTC    0.001f
#define SRC_Z  (NPML + 2)               // 34
#define REC_Z  (NPML + 2)               // 34

#define FSZ (NZP * NXPP)

#define BLKS_PER_SHOT 74
#define NBLK   (NSHOTS * BLKS_PER_SHOT) // 148
#define NTHR   1024
#define MAXC   3                        // velocity: scalar cells/thread
#define NXH    232                      // stress: pairs per row
#define MAXP   2                        // stress: pairs/thread (5*232/1024 -> 2)

// smem tile: row r <-> global row z0-2+r
//   r=0 guard(0), r=1 = z0-1 (vx/vz imported, sxz recomputed),
//   r=2..nrows+1 owned, r=nrows+2 = z1 (vx/vz imported, szz recomputed)
#define SROWS  8
#define SPITCH 480
#define FTILE  (SROWS * SPITCH)
#define SMEM_DYN (5 * FTILE * 4)        // 76800 B

// velocity flag bits
#define F_VAL  1
#define F_REC  2
#define F_TOP  4     // r == 2        -> publish vx,vz to lo
#define F_BOT  8     // r == nrows+1  -> publish vx,vz to hi
// stress pair flag bits
#define P_VAL  1
#define P_SRC0 2
#define P_SRC1 4

// ---------------- device state (static, no allocs) ----------------
__device__ float g_vx[NSHOTS][FSZ];
__device__ float g_vz[NSHOTS][FSZ];

__device__ unsigned g_flags[NBLK * 32];   // monotonic, 128B apart
__device__ double   g_part[NBLK];
__device__ unsigned g_done = 0u;

__device__ __forceinline__ void st_release_u32(unsigned* p, unsigned v)
{
    asm volatile("st.release.gpu.global.u32 [%0], %1;" :: "l"(p), "r"(v) : "memory");
}
__device__ __forceinline__ unsigned ld_acquire_u32(const unsigned* p)
{
    unsigned v;
    asm volatile("ld.acquire.gpu.global.u32 %0, [%1];" : "=r"(v) : "l"(p) : "memory");
    return v;
}
__device__ __forceinline__ void wait_flag(const unsigned* f, unsigned q)
{
    while ((int)(ld_acquire_u32(f) - q) < 0) { }
}

__global__ void __launch_bounds__(NTHR, 1)
fwi_persistent(const float* __restrict__ Vp,
               const float* __restrict__ Vs,
               const float* __restrict__ Den,
               const float* __restrict__ Stf,
               const float* __restrict__ Mask,
               const int*   __restrict__ ShotIds,
               float*       __restrict__ out)
{
    extern __shared__ float sm[];
    float* __restrict__ s_vx  = sm;
    float* __restrict__ s_vz  = sm + 1 * FTILE;
    float* __restrict__ s_sxx = sm + 2 * FTILE;
    float* __restrict__ s_szz = sm + 3 * FTILE;
    float* __restrict__ s_sxz = sm + 4 * FTILE;

    const int b   = blockIdx.x;
    const int s   = b / BLKS_PER_SHOT;
    const int kk  = b - s * BLKS_PER_SHOT;
    const int z0  = (kk * NZP) / BLKS_PER_SHOT;
    const int z1  = ((kk + 1) * NZP) / BLKS_PER_SHOT;
    const int nrows  = z1 - z0;
    const int ncells = nrows * NXP;
    const int npairs = nrows * NXH;
    const int tid = threadIdx.x;

    const int nb_lo = (kk > 0)                 ? b - 1 : -1;
    const int nb_hi = (kk < BLKS_PER_SHOT - 1) ? b + 1 : -1;

    float* __restrict__ vxg = g_vx[s];
    float* __restrict__ vzg = g_vz[s];

    const int gbase = (z0 - 2) * NXPP;     // global offset of smem row 0

    unsigned  q      = *(volatile unsigned*)&g_flags[b * 32];   // replay-safe base
    unsigned* myflag = &g_flags[b * 32];

    // ---------- zero smem tiles ----------
    for (int c = tid; c < 5 * FTILE; c += NTHR) sm[c] = 0.0f;

    // ---------- coefficient helper (A = dt*(lam+2mu)/dx, C = dt*mu/dx) ----------
    auto coef = [&](int i, int j, float& dtr, float& dmp, float& a, float& cc) {
        int ip = min(max(i - NPML, 0), NZ - 1);
        int jp = min(max(j - NPML, 0), NX - 1);
        float vp  = Vp [ip * NX + jp];
        float vs  = Vs [ip * NX + jp];
        float den = Den[ip * NX + jp];
        float m   = Mask[i * NXP + j];
        vp  = m * vp  + (1.0f - m) * vp;
        vs  = m * vs  + (1.0f - m) * vs;
        den = m * den + (1.0f - m) * den;
        float mu  = vs * vs * den * 1e-6f;
        float lam = (vp * vp - 2.0f * vs * vs) * den * 1e-6f;
        const float inv_dx = 1.0f / DXC;
        a   = DTC * (lam + 2.0f * mu) * inv_dx;
        cc  = DTC * mu  * inv_dx;
        dtr = (DTC / den) * inv_dx;
        float a1 = (float)(NPML - i);
        float a2 = (float)(i - (NZP - 1 - NPML));
        float dz = fmaxf(a1, a2); dz = fminf(fmaxf(dz, 0.0f), (float)NPML) / (float)NPML;
        float b1 = (float)(NPML - j);
        float b2 = (float)(j - (NXP - 1 - NPML));
        float dxs = fmaxf(b1, b2); dxs = fminf(fmaxf(dxs, 0.0f), (float)NPML) / (float)NPML;
        dmp = expf(-0.1f * (dz * dz + dxs * dxs));
    };

    // ---------- velocity cells (scalar), boundary rows first ----------
    int   soff[MAXC], fl[MAXC];
    float cdamp[MAXC], cdtrho[MAXC];

    const int sid  = ShotIds[s];
    const int srcx = NPML + 20 + sid * ((NX - 40) / NSHOTS);
    const float* stf = Stf + sid * NSTEPS;

    #pragma unroll
    for (int k = 0; k < MAXC; ++k) {
        int c  = tid + k * NTHR;
        int v  = (c < ncells);
        int cc2 = v ? c : 0;
        int r, j;
        if (cc2 < NXP)          { r = 2;         j = cc2; }
        else if (cc2 < 2 * NXP) { r = nrows + 1; j = cc2 - NXP; }
        else { int e = cc2 - 2 * NXP; int rr = e / NXP; r = 3 + rr; j = e - rr * NXP; }
        int i = z0 - 2 + r;

        soff[k] = r * SPITCH + j;

        int f = v ? F_VAL : 0;
        if (v && i == REC_Z && j >= NPML && j < NPML + NX) f |= F_REC;
        if (v && r == 2)          f |= F_TOP;
        if (v && r == nrows + 1)  f |= F_BOT;
        fl[k] = f;

        float dtr, dmp, a, cc;
        coef(i, j, dtr, dmp, a, cc);
        cdtrho[k] = dtr; cdamp[k] = dmp;
    }

    // ---------- stress cell-pairs (float2) ----------
    int    poff[MAXP], pfl[MAXP];
    float2 pA[MAXP], pC[MAXP], pD[MAXP];

    #pragma unroll
    for (int k = 0; k < MAXP; ++k) {
        int p = tid + k * NTHR;
        int v = (p < npairs);
        int pp = v ? p : 0;
        int rr = pp / NXH;
        int jj = pp - rr * NXH;
        int r  = 2 + rr;
        int j  = 2 * jj;
        int i  = z0 - 2 + r;

        poff[k] = r * SPITCH + j;

        int f = v ? P_VAL : 0;
        if (v && i == SRC_Z) {
            if (j == srcx)     f |= P_SRC0;
            if (j + 1 == srcx) f |= P_SRC1;
        }
        pfl[k] = f;

        float d0, m0, a0, c0, d1, m1, a1, c1;
        coef(i, j,     d0, m0, a0, c0);
        coef(i, j + 1, d1, m1, a1, c1);
        pA[k] = make_float2(a0, a1);
        pC[k] = make_float2(c0, c1);
        pD[k] = make_float2(m0, m1);
    }

    // ---------- stress-halo recompute cells ----------
    const bool topH = (nb_lo >= 0 && tid < NXP);
    const bool botH = (nb_hi >= 0 && tid >= 512 && tid < 512 + NXP);
    float hCt = 0.0f, hdampT = 0.0f;           // top: mu coeff + damp (sxz)
    float hA = 0.0f, hCb = 0.0f, hdampB = 0.0f;// bottom: A, C + damp (szz)
    bool  srcB = false;
    if (topH) {
        float dtr, a;
        coef(z0 - 1, tid, dtr, hdampT, a, hCt);
    }
    if (botH) {
        int j = tid - 512;
        float dtr;
        coef(z1, j, dtr, hdampB, hA, hCb);
        srcB = (z1 == SRC_Z && j == srcx);
    }

    __syncthreads();   // smem zero + setup done (block-local)

    double acc = 0.0;

    const int topSO = 1 * SPITCH;              // row z0-1
    const int botSO = (nrows + 2) * SPITCH;    // row z1

    // ---- velocity body (scalar, owned rows) ----
    auto vcell = [&](int k) {
        const int f = fl[k];
        if (!(f & F_VAL)) return;
        const int so = soff[k];
        float sxx_c = s_sxx[so];
        float sxx_r = s_sxx[so + 1];
        float sxz_c = s_sxz[so];
        float sxz_u = s_sxz[so - SPITCH];
        float sxz_l = s_sxz[so - 1];
        float szz_c = s_szz[so];
        float szz_d = s_szz[so + SPITCH];
        float nvx = (s_vx[so] + cdtrho[k] * ((sxx_r - sxx_c) + (sxz_c - sxz_u))) * cdamp[k];
        float nvz = (s_vz[so] + cdtrho[k] * ((sxz_c - sxz_l) + (szz_d - szz_c))) * cdamp[k];
        s_vx[so] = nvx;
        s_vz[so] = nvz;
        if (f & (F_TOP | F_BOT)) {
            __stcg(&vxg[gbase + so], nvx);
            __stcg(&vzg[gbase + so], nvz);
        }
        if (f & F_REC) acc += (double)nvx * (double)nvx;
    };

    // ---- stress body (float2 pairs) ----
    auto scell = [&](int k, int t) {
        const int f = pfl[k];
        if (!(f & P_VAL)) return;
        const int so = poff[k];

        float2 vx_c = *(float2*)&s_vx[so];
        float  vx_m = s_vx[so - 1];
        float2 vx_d = *(float2*)&s_vx[so + SPITCH];
        float2 vz_c = *(float2*)&s_vz[so];
        float  vz_2 = s_vz[so + 2];
        float2 vz_u = *(float2*)&s_vz[so - SPITCH];
        float2 sxx  = *(float2*)&s_sxx[so];
        float2 szz  = *(float2*)&s_szz[so];
        float2 sxz  = *(float2*)&s_sxz[so];

        float dx0 = vx_c.x - vx_m;
        float dx1 = vx_c.y - vx_c.x;
        float dz0 = vz_c.x - vz_u.x;
        float dz1 = vz_c.y - vz_u.y;

        float B0 = pA[k].x - 2.0f * pC[k].x;
        float B1 = pA[k].y - 2.0f * pC[k].y;

        sxx.x = (sxx.x + pA[k].x * dx0 + B0 * dz0) * pD[k].x;
        sxx.y = (sxx.y + pA[k].y * dx1 + B1 * dz1) * pD[k].y;
        szz.x = (szz.x + B0 * dx0 + pA[k].x * dz0) * pD[k].x;
        szz.y = (szz.y + B1 * dx1 + pA[k].y * dz1) * pD[k].y;
        sxz.x = (sxz.x + pC[k].x * ((vx_d.x - vx_c.x) + (vz_c.y - vz_c.x))) * pD[k].x;
        sxz.y = (sxz.y + pC[k].y * ((vx_d.y - vx_c.y) + (vz_2   - vz_c.y))) * pD[k].y;

        if (f & P_SRC0) { float sv = stf[t] * DTC; sxx.x += sv; szz.x += sv; }
        if (f & P_SRC1) { float sv = stf[t] * DTC; sxx.y += sv; szz.y += sv; }

        *(float2*)&s_sxx[so] = sxx;
        *(float2*)&s_szz[so] = szz;
        *(float2*)&s_sxz[so] = sxz;
    };

    // ---------------- time loop ----------------
    for (int t = 0; t < NSTEPS; ++t) {
        // ===== velocity phase =====
        vcell(0);                                  // boundary rows z0, z1-1 first
        __syncthreads();
        ++q;
        if (tid == 0) st_release_u32(myflag, q);   // publish V(t) boundary
        vcell(1); vcell(2);                        // interior = mattress for handshake

        float hvx = 0.0f, hvz = 0.0f;
        if (topH) {
            wait_flag(&g_flags[nb_lo * 32], q);
            hvx = __ldcg(&vxg[(z0 - 1) * NXPP + tid]);
            hvz = __ldcg(&vzg[(z0 - 1) * NXPP + tid]);
        }
        if (botH) {
            int j = tid - 512;
            wait_flag(&g_flags[nb_hi * 32], q);
            hvx = __ldcg(&vxg[z1 * NXPP + j]);
            hvz = __ldcg(&vzg[z1 * NXPP + j]);
        }
        if (topH) { s_vx[topSO + tid] = hvx; s_vz[topSO + tid] = hvz; }
        if (botH) { int j = tid - 512; s_vx[botSO + j] = hvx; s_vz[botSO + j] = hvz; }
        __syncthreads();   // all velocity (owned + halos) ready

        // ===== stress phase (vectorized) + halo recompute =====
        scell(0, t); scell(1, t);

        if (topH) {   // sxz(z0-1): matches neighbor's owned formula
            const int so = topSO + tid;
            float v = (s_sxz[so] + hCt * ((s_vx[so + SPITCH] - s_vx[so])
                                        + (s_vz[so + 1]      - s_vz[so]))) * hdampT;
            s_sxz[so] = v;
        }
        if (botH) {   // szz(z1): same derivation (B = A - 2C) as owned pairs
            const int j  = tid - 512;
            const int so = botSO + j;
            float dx = s_vx[so] - s_vx[so - 1];
            float dz = s_vz[so] - s_vz[so - SPITCH];
            float Bb = hA - 2.0f * hCb;
            float v = (s_szz[so] + Bb * dx + hA * dz) * hdampB;
            if (srcB) v += stf[t] * DTC;
            s_szz[so] = v;
        }
        __syncthreads();
    }

    // ---------------- deterministic reduction ----------------
    __shared__ double sh[NTHR];
    sh[tid] = acc;
    __syncthreads();
    for (int o = NTHR / 2; o > 0; o >>= 1) {
        if (tid < o) sh[tid] += sh[tid + o];
        __syncthreads();
    }

    __shared__ int is_last;
    if (tid == 0) {
        g_part[b] = sh[0];
        __threadfence();
        unsigned ticket = atomicAdd(&g_done, 1u);
        is_last = ((ticket + 1u) % NBLK == 0u) ? 1 : 0;
    }
    __syncthreads();

    if (is_last) {
        __threadfence();
        double a = 0.0;
        if (tid < NBLK) a = __ldcg(&g_part[tid]);
        sh[tid] = a;
        __syncthreads();
        for (int o = NTHR / 2; o > 0; o >>= 1) {
            if (tid < o) sh[tid] += sh[tid + o];
            __syncthreads();
        }
        if (tid == 0) out[0] = (float)(0.5 * sh[0]);
    }
}

// ---------------- launcher ----------------
extern "C" void kernel_launch(void* const* d_in, const int* in_sizes, int n_in,
                              void* d_out, int out_size)
{
    const float* Vp      = (const float*)d_in[0];
    const float* Vs      = (const float*)d_in[1];
    const float* Den     = (const float*)d_in[2];
    const float* Stf     = (const float*)d_in[3];
    const float* Mask    = (const float*)d_in[4];
    const int*   ShotIds = (const int*)  d_in[5];
    float*       out     = (float*)d_out;
    (void)in_sizes; (void)n_in; (void)out_size;

    static int smem_set = 0;
    if (!smem_set) {
        cudaFuncSetAttribute(fwi_persistent,
                             cudaFuncAttributeMaxDynamicSharedMemorySize, SMEM_DYN);
        smem_set = 1;
    }

    fwi_persistent<<<NBLK, NTHR, SMEM_DYN>>>(Vp, Vs, Den, Stf, Mask, ShotIds, out);
}